// round 8
// baseline (speedup 1.0000x reference)
#include <cuda_runtime.h>
#include <cuda_bf16.h>
#include <math.h>
#include <stddef.h>

typedef __nv_bfloat16 bf16;

#define B_      256
#define T_      64
#define STOCH   32
#define DETER   1024
#define HIDDEN  1024
#define EMBED   1536
#define ACTD    6
#define ENS     5
#define OUTDIM  1216   // 6*STOCH + DETER
#define NCTA    128

// ---------------- scratch (device globals; no allocation allowed) ----------
__device__ __align__(16) bf16 g_WgruH[2048 * 3072];
__device__ __align__(16) bf16 g_WgruL[2048 * 3072];
__device__ __align__(16) bf16 g_WobsH[2560 * 1024];
__device__ __align__(16) bf16 g_WobsL[2560 * 1024];
__device__ __align__(16) bf16 g_WensH[ENS * 1024 * 1024];
__device__ __align__(16) bf16 g_WensL[ENS * 1024 * 1024];
__device__ __align__(16) bf16 g_embH[B_ * T_ * EMBED];
__device__ __align__(16) bf16 g_embL[B_ * T_ * EMBED];
__device__ __align__(16) bf16 g_xH[B_ * HIDDEN];
__device__ __align__(16) bf16 g_xL[B_ * HIDDEN];
__device__ __align__(16) bf16 g_deterH[B_ * DETER];
__device__ __align__(16) bf16 g_deterL[B_ * DETER];

__device__ __align__(16) float g_deter[B_ * DETER];
__device__ __align__(16) float g_pp0s[4][B_ * 3072];   // gruX K-chunk partials
__device__ __align__(16) float g_pp1s[4][B_ * 3072];   // gruD K-chunk partials
__device__ __align__(16) float g_xops[4][B_ * 1024];   // obsD K-chunk partials
__device__ __align__(16) float g_hps[4][B_ * 1024];    // ens K-chunk partials
__device__ __align__(16) float g_xope[B_ * T_ * 1024]; // embed@Wobs, all t
__device__ __align__(16) float g_WodT[64 * 1024];
__device__ __align__(16) float g_WedT[ENS * 64 * 1024];
__device__ unsigned g_count;

// ---------------- fast-math helpers (MUFU ex2/rcp) --------------------------
#define LOG2E 1.4426950408889634f
__device__ __forceinline__ float fex2(float x) {
    float r; asm("ex2.approx.f32 %0, %1;" : "=f"(r) : "f"(x)); return r;
}
__device__ __forceinline__ float frcpa(float x) {
    float r; asm("rcp.approx.f32 %0, %1;" : "=f"(r) : "f"(x)); return r;
}
__device__ __forceinline__ float elu1(float x) {
    return x > 0.f ? x : fex2(LOG2E * x) - 1.f;
}
__device__ __forceinline__ float sigm(float x) {
    return frcpa(1.f + fex2(-LOG2E * x));
}
__device__ __forceinline__ float ftanh(float x) {
    float e = fex2(2.f * LOG2E * x);
    return 1.f - 2.f * frcpa(e + 1.f);
}
__device__ __forceinline__ float splus(float x) {
    return fmaxf(x, 0.f) + log1pf(expf(-fabsf(x)));
}

// ---------------- setup kernels ---------------------------------------------
__global__ void k_init() {
    int i = blockIdx.x * blockDim.x + threadIdx.x;
    if (i == 0) g_count = 0;
    if (i < B_ * DETER) {
        g_deter[i] = 0.f;
        g_deterH[i] = __float2bfloat16(0.f);
        g_deterL[i] = __float2bfloat16(0.f);
    }
}

__global__ void k_split(const float* __restrict__ src, bf16* __restrict__ hi,
                        bf16* __restrict__ lo, int n) {
    for (int i = blockIdx.x * blockDim.x + threadIdx.x; i < n;
         i += gridDim.x * blockDim.x) {
        float v = src[i];
        bf16 h = __float2bfloat16(v);
        hi[i] = h;
        lo[i] = __float2bfloat16(v - __bfloat162float(h));
    }
}

__global__ void k_transpose(const float* __restrict__ Wod,
                            const float* __restrict__ Wed) {
    int i = blockIdx.x * blockDim.x + threadIdx.x;  // 6*65536
    int part = i >> 16;
    int r = i & 65535;
    int j = r >> 10;
    int k = r & 1023;
    if (part == 0) {
        g_WodT[r] = Wod[k * 64 + j];
    } else {
        int h = part - 1;
        g_WedT[(size_t)h * 65536 + r] = Wed[(size_t)h * 65536 + k * 64 + j];
    }
}

// inp for t=0 (stoch carry is zero)
__global__ void k_inp0(const float* __restrict__ action,
                       const unsigned char* __restrict__ is_first,
                       const float* __restrict__ W_inp,
                       const float* __restrict__ b_inp) {
    int b = blockIdx.x;
    int tid = threadIdx.x;
    __shared__ float in[STOCH + ACTD];
    float m = is_first[b * T_] ? 0.f : 1.f;
    if (tid < STOCH)
        in[tid] = 0.f;
    else if (tid < STOCH + ACTD)
        in[tid] = action[(size_t)b * T_ * ACTD + (tid - STOCH)] * m;
    __syncthreads();
    for (int h = tid; h < HIDDEN; h += 256) {
        float s = b_inp[h];
#pragma unroll
        for (int k = 0; k < STOCH + ACTD; k++)
            s = fmaf(in[k], W_inp[k * HIDDEN + h], s);
        float v = elu1(s);
        bf16 hv = __float2bfloat16(v);
        g_xH[b * HIDDEN + h] = hv;
        g_xL[b * HIDDEN + h] = __float2bfloat16(v - __bfloat162float(hv));
    }
}

// ---------------- MMA primitives --------------------------------------------
__device__ __forceinline__ unsigned saddr(const void* p) {
    return (unsigned)__cvta_generic_to_shared(p);
}
__device__ __forceinline__ void ldsm4(unsigned a, unsigned* r) {
    asm volatile("ldmatrix.sync.aligned.m8n8.x4.shared.b16 {%0,%1,%2,%3}, [%4];"
                 : "=r"(r[0]), "=r"(r[1]), "=r"(r[2]), "=r"(r[3]) : "r"(a));
}
__device__ __forceinline__ void ldsm4t(unsigned a, unsigned* r) {
    asm volatile("ldmatrix.sync.aligned.m8n8.x4.trans.shared.b16 {%0,%1,%2,%3}, [%4];"
                 : "=r"(r[0]), "=r"(r[1]), "=r"(r[2]), "=r"(r[3]) : "r"(a));
}
__device__ __forceinline__ void mma16816(float* c, const unsigned* a,
                                         unsigned b0, unsigned b1) {
    asm volatile(
        "mma.sync.aligned.m16n8k16.row.col.f32.bf16.bf16.f32 "
        "{%0,%1,%2,%3},{%4,%5,%6,%7},{%8,%9},{%0,%1,%2,%3};"
        : "+f"(c[0]), "+f"(c[1]), "+f"(c[2]), "+f"(c[3])
        : "r"(a[0]), "r"(a[1]), "r"(a[2]), "r"(a[3]), "r"(b0), "r"(b1));
}

// ---------------- standalone multi-sub GEMM (setup / prologue) ---------------
struct SubTC {
    const bf16* aH; const bf16* aL; long long lda;
    const bf16* wH; const bf16* wL; long long ldw;
    int K;
    const float* bias;
    float* C; long long ldc;
    int mt;
};
struct ParamsTC { SubTC s[8]; int start[9]; int nsub; };

__global__ void __launch_bounds__(128) gemm_tc(ParamsTC p) {
    const int w = blockIdx.x;
    int si = 0;
#pragma unroll
    for (int i = 1; i < 8; i++)
        if (i < p.nsub && w >= p.start[i]) si = i;
    SubTC s = p.s[si];
    const int r = w - p.start[si];
    const int bm = (r % s.mt) << 6, bn = (r / s.mt) << 6;
    const float* bias = s.bias;

    const int tid = threadIdx.x, lane = tid & 31, warp = tid >> 5;
    const int warpM = warp & 1, warpN = warp >> 1;

    __shared__ __align__(16) bf16 AsH[2][64][32], AsL[2][64][32];
    __shared__ __align__(16) bf16 BsH[2][32][64], BsL[2][32][64];

    const int ar = tid >> 2, ac = tid & 3;
    const int apc = (ac ^ ((ar >> 1) & 3)) * 8;
    const int br = tid >> 3, bc = tid & 7;
    const int bpc = (bc ^ (br & 7)) * 8;

    const bf16* aHp = s.aH + (long long)(bm + ar) * s.lda + ac * 8;
    const bf16* aLp = s.aL + (long long)(bm + ar) * s.lda + ac * 8;
    const bf16* wHp = s.wH + (long long)br * s.ldw + bn + bc * 8;
    const bf16* wLp = s.wL + (long long)br * s.ldw + bn + bc * 8;
    const long long aRowStep = 32 * s.lda;
    const long long bRowStep = 16 * s.ldw;
    const long long bKStep = 32 * s.ldw;

    uint4 pAH0, pAH1, pAL0, pAL1, pBH0, pBH1, pBL0, pBL1;
    auto loadStage = [&](int kt) {
        const bf16* a = aHp + kt * 32;
        pAH0 = *(const uint4*)a;
        pAH1 = *(const uint4*)(a + aRowStep);
        const bf16* al = aLp + kt * 32;
        pAL0 = *(const uint4*)al;
        pAL1 = *(const uint4*)(al + aRowStep);
        const bf16* b = wHp + (long long)kt * bKStep;
        pBH0 = *(const uint4*)b;
        pBH1 = *(const uint4*)(b + bRowStep);
        const bf16* bl = wLp + (long long)kt * bKStep;
        pBL0 = *(const uint4*)bl;
        pBL1 = *(const uint4*)(bl + bRowStep);
    };
    auto storeStage = [&](int bb) {
        *(uint4*)&AsH[bb][ar][apc] = pAH0;
        *(uint4*)&AsH[bb][ar + 32][apc] = pAH1;
        *(uint4*)&AsL[bb][ar][apc] = pAL0;
        *(uint4*)&AsL[bb][ar + 32][apc] = pAL1;
        *(uint4*)&BsH[bb][br][bpc] = pBH0;
        *(uint4*)&BsH[bb][br + 16][bpc] = pBH1;
        *(uint4*)&BsL[bb][br][bpc] = pBL0;
        *(uint4*)&BsL[bb][br + 16][bpc] = pBL1;
    };

    float acc[2][4][4] = {};
    const int lrow = lane & 15, lsel = lane >> 4;

    loadStage(0);
    storeStage(0);
    __syncthreads();

    const int nt = s.K >> 5;
    int buf = 0;
    for (int kt = 0; kt < nt; kt++) {
        if (kt + 1 < nt) loadStage(kt + 1);
#pragma unroll
        for (int ks = 0; ks < 2; ks++) {
            unsigned aHf[2][4], aLf[2][4], bHf[2][4], bLf[2][4];
#pragma unroll
            for (int tm = 0; tm < 2; tm++) {
                int rr = warpM * 32 + tm * 16 + lrow;
                int pc = ((ks * 2 + lsel) ^ ((rr >> 1) & 3)) * 8;
                ldsm4(saddr(&AsH[buf][rr][pc]), aHf[tm]);
                ldsm4(saddr(&AsL[buf][rr][pc]), aLf[tm]);
            }
            int kr = ks * 16 + lrow;
#pragma unroll
            for (int tn = 0; tn < 2; tn++) {
                int pc = ((warpN * 4 + tn * 2 + lsel) ^ (kr & 7)) * 8;
                ldsm4t(saddr(&BsH[buf][kr][pc]), bHf[tn]);
                ldsm4t(saddr(&BsL[buf][kr][pc]), bLf[tn]);
            }
#pragma unroll
            for (int tm = 0; tm < 2; tm++)
#pragma unroll
                for (int j = 0; j < 4; j++) {
                    unsigned bh0 = bHf[j >> 1][(j & 1) * 2];
                    unsigned bh1 = bHf[j >> 1][(j & 1) * 2 + 1];
                    unsigned bl0 = bLf[j >> 1][(j & 1) * 2];
                    unsigned bl1 = bLf[j >> 1][(j & 1) * 2 + 1];
                    mma16816(acc[tm][j], aHf[tm], bh0, bh1);
                    mma16816(acc[tm][j], aLf[tm], bh0, bh1);
                    mma16816(acc[tm][j], aHf[tm], bl0, bl1);
                }
        }
        if (kt + 1 < nt) storeStage(buf ^ 1);
        __syncthreads();
        buf ^= 1;
    }

    const int g = lane >> 2, tg = lane & 3;
#pragma unroll
    for (int tm = 0; tm < 2; tm++) {
        int row = bm + warpM * 32 + tm * 16 + g;
#pragma unroll
        for (int j = 0; j < 4; j++) {
            int col = bn + warpN * 32 + j * 8 + tg * 2;
            float bx = bias ? bias[col] : 0.f;
            float by = bias ? bias[col + 1] : 0.f;
            float2 v0 = { acc[tm][j][0] + bx, acc[tm][j][1] + by };
            float2 v1 = { acc[tm][j][2] + bx, acc[tm][j][3] + by };
            *(float2*)&s.C[(long long)row * s.ldc + col] = v0;
            *(float2*)&s.C[(long long)(row + 8) * s.ldc + col] = v1;
        }
    }
}

// ---------------- half-CTA GEMM unit (K=256, inside step kernel) ------------
__device__ __forceinline__ void half_bar(int half) {
    asm volatile("bar.sync %0, 128;" :: "r"(1 + half) : "memory");
}

__device__ __noinline__ void gemm_unit(
    const bf16* __restrict__ aH, const bf16* __restrict__ aL, int lda,
    const bf16* __restrict__ wH, const bf16* __restrict__ wL, int ldw,
    const float* __restrict__ bias, float* __restrict__ C, int ldc,
    int bm, int bn, int htid, int half, char* gsm)
{
    bf16* AsH = (bf16*)gsm;            // 2 bufs x 2048
    bf16* AsL = AsH + 4096;
    bf16* BsH = AsL + 4096;
    bf16* BsL = BsH + 4096;
    const int lane = htid & 31, warp = htid >> 5;
    const int warpM = warp & 1, warpN = warp >> 1;

    const int ar = htid >> 2, ac = htid & 3;
    const int apc = (ac ^ ((ar >> 1) & 3)) * 8;
    const int br = htid >> 3, bc = htid & 7;
    const int bpc = (bc ^ (br & 7)) * 8;

    const bf16* aHp = aH + (long long)(bm + ar) * lda + ac * 8;
    const bf16* aLp = aL + (long long)(bm + ar) * lda + ac * 8;
    const bf16* wHp = wH + (long long)br * ldw + bn + bc * 8;
    const bf16* wLp = wL + (long long)br * ldw + bn + bc * 8;
    const long long aRowStep = (long long)32 * lda;
    const long long bRowStep = (long long)16 * ldw;
    const long long bKStep = (long long)32 * ldw;

    uint4 pAH0, pAH1, pAL0, pAL1, pBH0, pBH1, pBL0, pBL1;
    auto loadStage = [&](int kt) {
        const bf16* a = aHp + kt * 32;
        pAH0 = *(const uint4*)a;
        pAH1 = *(const uint4*)(a + aRowStep);
        const bf16* al = aLp + kt * 32;
        pAL0 = *(const uint4*)al;
        pAL1 = *(const uint4*)(al + aRowStep);
        const bf16* b = wHp + (long long)kt * bKStep;
        pBH0 = *(const uint4*)b;
        pBH1 = *(const uint4*)(b + bRowStep);
        const bf16* bl = wLp + (long long)kt * bKStep;
        pBL0 = *(const uint4*)bl;
        pBL1 = *(const uint4*)(bl + bRowStep);
    };
    auto storeStage = [&](int bb) {
        *(uint4*)&AsH[bb * 2048 + ar * 32 + apc] = pAH0;
        *(uint4*)&AsH[bb * 2048 + (ar + 32) * 32 + apc] = pAH1;
        *(uint4*)&AsL[bb * 2048 + ar * 32 + apc] = pAL0;
        *(uint4*)&AsL[bb * 2048 + (ar + 32) * 32 + apc] = pAL1;
        *(uint4*)&BsH[bb * 2048 + br * 64 + bpc] = pBH0;
        *(uint4*)&BsH[bb * 2048 + (br + 16) * 64 + bpc] = pBH1;
        *(uint4*)&BsL[bb * 2048 + br * 64 + bpc] = pBL0;
        *(uint4*)&BsL[bb * 2048 + (br + 16) * 64 + bpc] = pBL1;
    };

    float acc[2][4][4] = {};
    const int lrow = lane & 15, lsel = lane >> 4;

    loadStage(0);
    storeStage(0);
    half_bar(half);

    int buf = 0;
#pragma unroll 1
    for (int kt = 0; kt < 8; kt++) {
        if (kt + 1 < 8) loadStage(kt + 1);
#pragma unroll
        for (int ks = 0; ks < 2; ks++) {
            unsigned aHf[2][4], aLf[2][4], bHf[2][4], bLf[2][4];
#pragma unroll
            for (int tm = 0; tm < 2; tm++) {
                int rr = warpM * 32 + tm * 16 + lrow;
                int pc = ((ks * 2 + lsel) ^ ((rr >> 1) & 3)) * 8;
                ldsm4(saddr(&AsH[buf * 2048 + rr * 32 + pc]), aHf[tm]);
                ldsm4(saddr(&AsL[buf * 2048 + rr * 32 + pc]), aLf[tm]);
            }
            int kr = ks * 16 + lrow;
#pragma unroll
            for (int tn = 0; tn < 2; tn++) {
                int pc = ((warpN * 4 + tn * 2 + lsel) ^ (kr & 7)) * 8;
                ldsm4t(saddr(&BsH[buf * 2048 + kr * 64 + pc]), bHf[tn]);
                ldsm4t(saddr(&BsL[buf * 2048 + kr * 64 + pc]), bLf[tn]);
            }
#pragma unroll
            for (int tm = 0; tm < 2; tm++)
#pragma unroll
                for (int j = 0; j < 4; j++) {
                    unsigned bh0 = bHf[j >> 1][(j & 1) * 2];
                    unsigned bh1 = bHf[j >> 1][(j & 1) * 2 + 1];
                    unsigned bl0 = bLf[j >> 1][(j & 1) * 2];
                    unsigned bl1 = bLf[j >> 1][(j & 1) * 2 + 1];
                    mma16816(acc[tm][j], aHf[tm], bh0, bh1);
                    mma16816(acc[tm][j], aLf[tm], bh0, bh1);
                    mma16816(acc[tm][j], aHf[tm], bl0, bl1);
                }
        }
        if (kt + 1 < 8) storeStage(buf ^ 1);
        half_bar(half);
        buf ^= 1;
    }

    const int g = lane >> 2, tg = lane & 3;
#pragma unroll
    for (int tm = 0; tm < 2; tm++) {
        int row = bm + warpM * 32 + tm * 16 + g;
#pragma unroll
        for (int j = 0; j < 4; j++) {
            int col = bn + warpN * 32 + j * 8 + tg * 2;
            float bx = bias ? bias[col] : 0.f;
            float by = bias ? bias[col + 1] : 0.f;
            float2 v0 = { acc[tm][j][0] + bx, acc[tm][j][1] + by };
            float2 v1 = { acc[tm][j][2] + bx, acc[tm][j][3] + by };
            *(float2*)&C[(long long)row * ldc + col] = v0;
            *(float2*)&C[(long long)(row + 8) * ldc + col] = v1;
        }
    }
}

// ---------------- grid barrier (128 CTAs, absolute targets) ------------------
__device__ __forceinline__ void grid_bar(unsigned target) {
    __syncthreads();
    if (threadIdx.x == 0) {
        __threadfence();
        atomicAdd(&g_count, 1u);
        while (*(volatile unsigned*)&g_count < target) { }
        __threadfence();
    }
    __syncthreads();
}

// ---------------- fused step kernel ------------------------------------------
__global__ void __launch_bounds__(256, 1) k_step(
    int t, int last, unsigned barBase,
    const int* __restrict__ ens_idx,
    const float* __restrict__ ln_g, const float* __restrict__ ln_b,
    const unsigned char* __restrict__ is_first,
    const float* __restrict__ b_gru, const float* __restrict__ b_obs,
    const float* __restrict__ b_ens,
    const float* __restrict__ bod, const float* __restrict__ bed,
    const float* __restrict__ eps_post, const float* __restrict__ eps_prior,
    const float* __restrict__ action,
    const float* __restrict__ W_inp, const float* __restrict__ b_inp,
    float* __restrict__ out)
{
    extern __shared__ __align__(16) char smem[];
    const int tid = threadIdx.x;
    const int cta = blockIdx.x;
    const int half = tid >> 7, htid = tid & 127;
    const int unit = cta * 2 + half;
    const int lane = tid & 31, wid = tid >> 5;
    const int idx = __ldg(&ens_idx[t]);
    float* fsm = (float*)smem;

    // ================= phase 0: gate for batches cta, cta+128 =================
    {
        float* pv = fsm;          // 3072
        float* red = fsm + 3072;  // 20
#pragma unroll 1
        for (int ib = 0; ib < 2; ib++) {
            int b = cta + ib * 128;
            float m = is_first[b * T_ + t] ? 0.f : 1.f;
            float4* pv4 = (float4*)pv;
            float s = 0.f, ss = 0.f;
#pragma unroll
            for (int i = 0; i < 3; i++) {
                int ix = tid + i * 256;
                int gi = b * 768 + ix;
                float4 a0 = ((const float4*)g_pp0s[0])[gi];
                float4 a1 = ((const float4*)g_pp0s[1])[gi];
                float4 a2 = ((const float4*)g_pp0s[2])[gi];
                float4 a3 = ((const float4*)g_pp0s[3])[gi];
                float4 c0 = ((const float4*)g_pp1s[0])[gi];
                float4 c1 = ((const float4*)g_pp1s[1])[gi];
                float4 c2 = ((const float4*)g_pp1s[2])[gi];
                float4 c3 = ((const float4*)g_pp1s[3])[gi];
                float4 v;
                v.x = fmaf(m, c0.x + c1.x + c2.x + c3.x, a0.x + a1.x + a2.x + a3.x);
                v.y = fmaf(m, c0.y + c1.y + c2.y + c3.y, a0.y + a1.y + a2.y + a3.y);
                v.z = fmaf(m, c0.z + c1.z + c2.z + c3.z, a0.z + a1.z + a2.z + a3.z);
                v.w = fmaf(m, c0.w + c1.w + c2.w + c3.w, a0.w + a1.w + a2.w + a3.w);
                pv4[ix] = v;
                s += v.x + v.y + v.z + v.w;
                ss = fmaf(v.x, v.x, ss); ss = fmaf(v.y, v.y, ss);
                ss = fmaf(v.z, v.z, ss); ss = fmaf(v.w, v.w, ss);
            }
            for (int o = 16; o; o >>= 1) {
                s  += __shfl_down_sync(~0u, s, o);
                ss += __shfl_down_sync(~0u, ss, o);
            }
            if (lane == 0) { red[wid] = s; red[8 + wid] = ss; }
            __syncthreads();
            if (tid == 0) {
                float S = 0.f, SS = 0.f;
                for (int i = 0; i < 8; i++) { S += red[i]; SS += red[8 + i]; }
                float mean = S * (1.f / 3072.f);
                float var  = SS * (1.f / 3072.f) - mean * mean;
                red[16] = mean;
                red[17] = rsqrtf(var + 1e-5f);
            }
            __syncthreads();
            float mean = red[16], rstd = red[17];
            float* orow = out + ((size_t)b * T_ + t) * OUTDIM + 192;
#pragma unroll
            for (int i = 0; i < 4; i++) {
                int ix = tid + i * 256;
                float r = (pv[ix]        - mean) * rstd * ln_g[ix]        + ln_b[ix];
                float c = (pv[1024 + ix] - mean) * rstd * ln_g[1024 + ix] + ln_b[1024 + ix];
                float u = (pv[2048 + ix] - mean) * rstd * ln_g[2048 + ix] + ln_b[2048 + ix];
                float reset  = sigm(r);
                float cand   = ftanh(reset * c);
                float update = sigm(u - 1.0f);
                float dn = update * cand + (1.f - update) * (m * g_deter[b * DETER + ix]);
                g_deter[b * DETER + ix] = dn;
                bf16 hv = __float2bfloat16(dn);
                g_deterH[b * DETER + ix] = hv;
                g_deterL[b * DETER + ix] = __float2bfloat16(dn - __bfloat162float(hv));
                orow[ix] = dn;
            }
            __syncthreads();
        }
    }
    grid_bar(barBase + NCTA);

    // ================= phase 1: obsD (256) + ens (256) tiles ==================
    {
        char* gsm = smem + half * 32768;
        for (int w = unit; w < 512; w += 256) {
            if (w < 256) {
                int c = w >> 6, r = w & 63;
                int bm = (r & 3) << 6, bn = (r >> 2) << 6;
                gemm_unit(g_deterH + c * 256, g_deterL + c * 256, DETER,
                          g_WobsH + (size_t)(c * 256) * 1024,
                          g_WobsL + (size_t)(c * 256) * 1024, 1024,
                          c == 0 ? b_obs : nullptr,
                          g_xops[c], 1024, bm, bn, htid, half, gsm);
            } else {
                int v = w - 256;
                int c = v >> 6, r = v & 63;
                int bm = (r & 3) << 6, bn = (r >> 2) << 6;
                gemm_unit(g_deterH + c * 256, g_deterL + c * 256, DETER,
                          g_WensH + (size_t)idx * 1048576 + (size_t)(c * 256) * 1024,
                          g_WensL + (size_t)idx * 1048576 + (size_t)(c * 256) * 1024,
                          1024,
                          c == 0 ? (b_ens + idx * HIDDEN) : nullptr,
                          g_hps[c], 1024, bm, bn, htid, half, gsm);
            }
        }
    }
    grid_bar(barBase + 2 * NCTA);

    // ================= phase 2: prior + post + inp(t+1) =======================
    {
        float* sh = fsm;            // 2048
        float* sval = fsm + 2048;   // 128
        float* spost = fsm + 2176;  // 64
        float* sin2 = fsm + 2240;   // 2*40

        // ---- prior ----
        float4* sh4 = (float4*)sh;
#pragma unroll
        for (int ib = 0; ib < 2; ib++) {
            int b = cta + ib * 128;
            int gi = b * 256 + tid;
            float4 h0 = ((const float4*)g_hps[0])[gi];
            float4 h1 = ((const float4*)g_hps[1])[gi];
            float4 h2 = ((const float4*)g_hps[2])[gi];
            float4 h3 = ((const float4*)g_hps[3])[gi];
            float4 e = { elu1(h0.x + h1.x + h2.x + h3.x),
                         elu1(h0.y + h1.y + h2.y + h3.y),
                         elu1(h0.z + h1.z + h2.z + h3.z),
                         elu1(h0.w + h1.w + h2.w + h3.w) };
            sh4[ib * 256 + tid] = e;
        }
        __syncthreads();
        for (int oo = wid; oo < 64; oo += 8) {
            const float4* w4 = (const float4*)(g_WedT + (size_t)idx * 65536 + oo * 1024);
            const float4* a4 = (const float4*)sh;
            const float4* b4 = (const float4*)(sh + 1024);
            float s0 = 0.f, s1 = 0.f;
#pragma unroll
            for (int k = lane; k < 256; k += 32) {
                float4 w = w4[k], a = a4[k], b = b4[k];
                s0 += w.x * a.x + w.y * a.y + w.z * a.z + w.w * a.w;
                s1 += w.x * b.x + w.y * b.y + w.z * b.z + w.w * b.w;
            }
            for (int off = 16; off; off >>= 1) {
                s0 += __shfl_down_sync(~0u, s0, off);
                s1 += __shfl_down_sync(~0u, s1, off);
            }
            if (lane == 0) {
                float bb = bed[idx * 64 + oo];
                sval[oo] = s0 + bb;
                sval[64 + oo] = s1 + bb;
            }
        }
        __syncthreads();
        if (tid < 64) {
            int ib = tid >> 5, j = tid & 31;
            int b = cta + ib * 128;
            const float* sv = sval + ib * 64;
            float* orow = out + ((size_t)b * T_ + t) * OUTDIM;
            float pm = sv[j];
            float ps = splus(sv[32 + j]) + 0.1f;
            float ep = eps_prior[((size_t)b * T_ + t) * STOCH + j];
            orow[96 + j]  = pm;
            orow[128 + j] = ps;
            orow[160 + j] = fmaf(ps, ep, pm);
        }
        __syncthreads();

        // ---- post ----
#pragma unroll
        for (int ib = 0; ib < 2; ib++) {
            int b = cta + ib * 128;
            int gi = b * 256 + tid;
            float4 x0 = ((const float4*)g_xops[0])[gi];
            float4 x1 = ((const float4*)g_xops[1])[gi];
            float4 x2 = ((const float4*)g_xops[2])[gi];
            float4 x3 = ((const float4*)g_xops[3])[gi];
            float4 xe = ((const float4*)g_xope)[((size_t)b * T_ + t) * 256 + tid];
            float4 f = { elu1(x0.x + x1.x + x2.x + x3.x + xe.x),
                         elu1(x0.y + x1.y + x2.y + x3.y + xe.y),
                         elu1(x0.z + x1.z + x2.z + x3.z + xe.z),
                         elu1(x0.w + x1.w + x2.w + x3.w + xe.w) };
            sh4[ib * 256 + tid] = f;
        }
        __syncthreads();
        for (int oo = wid; oo < 64; oo += 8) {
            const float4* w4 = (const float4*)(g_WodT + oo * 1024);
            const float4* a4 = (const float4*)sh;
            const float4* b4 = (const float4*)(sh + 1024);
            float s0 = 0.f, s1 = 0.f;
#pragma unroll
            for (int k = lane; k < 256; k += 32) {
                float4 w = w4[k], a = a4[k], b = b4[k];
                s0 += w.x * a.x + w.y * a.y + w.z * a.z + w.w * a.w;
                s1 += w.x * b.x + w.y * b.y + w.z * b.z + w.w * b.w;
            }
            for (int off = 16; off; off >>= 1) {
                s0 += __shfl_down_sync(~0u, s0, off);
                s1 += __shfl_down_sync(~0u, s1, off);
            }
            if (lane == 0) {
                float bb = bod[oo];
                sval[oo] = s0 + bb;
                sval[64 + oo] = s1 + bb;
            }
        }
        __syncthreads();
        if (tid < 64) {
            int ib = tid >> 5, j = tid & 31;
            int b = cta + ib * 128;
            const float* sv = sval + ib * 64;
            float* orow = out + ((size_t)b * T_ + t) * OUTDIM;
            float om = sv[j];
            float os = splus(sv[32 + j]) + 0.1f;
            float eq = eps_post[((size_t)b * T_ + t) * STOCH + j];
            float post = fmaf(os, eq, om);
            orow[j]      = om;
            orow[32 + j] = os;
            orow[64 + j] = post;
            spost[ib * 32 + j] = post;
        }
        if (last) return;
        __syncthreads();

        // ---- inp(t+1) ----
        if (tid < 38) {
            float m = is_first[cta * T_ + t + 1] ? 0.f : 1.f;
            sin2[tid] = (tid < 32 ? spost[tid]
                         : action[((size_t)cta * T_ + t + 1) * ACTD + tid - 32]) * m;
        } else if (tid < 76) {
            int j = tid - 38;
            int b1 = cta + 128;
            float m = is_first[b1 * T_ + t + 1] ? 0.f : 1.f;
            sin2[40 + j] = (j < 32 ? spost[32 + j]
                            : action[((size_t)b1 * T_ + t + 1) * ACTD + j - 32]) * m;
        }
        __syncthreads();
#pragma unroll
        for (int hh = 0; hh < 4; hh++) {
            int h = tid + hh * 256;
            float s0 = b_inp[h], s1 = s0;
#pragma unroll
            for (int k = 0; k < STOCH + ACTD; k++) {
                float w = W_inp[k * HIDDEN + h];
                s0 = fmaf(sin2[k], w, s0);
                s1 = fmaf(sin2[40 + k], w, s1);
            }
            float v0 = elu1(s0), v1 = elu1(s1);
            bf16 h0 = __float2bfloat16(v0), h1 = __float2bfloat16(v1);
            g_xH[cta * HIDDEN + h] = h0;
            g_xL[cta * HIDDEN + h] = __float2bfloat16(v0 - __bfloat162float(h0));
            g_xH[(cta + 128) * HIDDEN + h] = h1;
            g_xL[(cta + 128) * HIDDEN + h] = __float2bfloat16(v1 - __bfloat162float(h1));
        }
    }
    grid_bar(barBase + 3 * NCTA);

    // ================= phase 3: gruX (768) + gruD (768) tiles =================
    {
        char* gsm = smem + half * 32768;
        for (int w = unit; w < 1536; w += 256) {
            if (w < 768) {
                int c = w / 192, r = w % 192;
                int bm = (r & 3) << 6, bn = (r >> 2) << 6;
                gemm_unit(g_xH + c * 256, g_xL + c * 256, HIDDEN,
                          g_WgruH + (size_t)(c * 256) * 3072,
                          g_WgruL + (size_t)(c * 256) * 3072, 3072,
                          c == 0 ? b_gru : nullptr,
                          g_pp0s[c], 3072, bm, bn, htid, half, gsm);
            } else {
                int v = w - 768;
                int c = v / 192, r = v % 192;
                int bm = (r & 3) << 6, bn = (r >> 2) << 6;
                gemm_unit(g_deterH + c * 256, g_deterL + c * 256, DETER,
                          g_WgruH + (size_t)(1024 + c * 256) * 3072,
                          g_WgruL + (size_t)(1024 + c * 256) * 3072, 3072,
                          nullptr,
                          g_pp1s[c], 3072, bm, bn, htid, half, gsm);
            }
        }
    }
}

// ---------------- launch ----------------------------------------------------
extern "C" void kernel_launch(void* const* d_in, const int* in_sizes, int n_in,
                              void* d_out, int out_size) {
    const float* embed      = (const float*)d_in[0];
    const float* action     = (const float*)d_in[1];
    const float* eps_post   = (const float*)d_in[2];
    const float* eps_prior  = (const float*)d_in[3];
    const unsigned char* is_first = (const unsigned char*)d_in[4];
    const int*   ens_idx    = (const int*)d_in[5];
    const float* W_gru      = (const float*)d_in[6];
    const float* b_gru      = (const float*)d_in[7];
    const float* ln_g       = (const float*)d_in[8];
    const float* ln_b       = (const float*)d_in[9];
    const float* W_inp      = (const float*)d_in[10];
    const float* b_inp      = (const float*)d_in[11];
    const float* W_obs      = (const float*)d_in[12];
    const float* b_obs      = (const float*)d_in[13];
    const float* W_ens      = (const float*)d_in[14];
    const float* b_ens      = (const float*)d_in[15];
    const float* W_obs_dist = (const float*)d_in[16];
    const float* b_obs_dist = (const float*)d_in[17];
    const float* W_ens_dist = (const float*)d_in[18];
    const float* b_ens_dist = (const float*)d_in[19];
    float* out = (float*)d_out;

    bf16 *wgH, *wgL, *woH, *woL, *weH, *weL, *emH, *emL, *xH, *xL, *dH, *dL;
    float *pxope;
    float *pp0[4], *pp1[4];
    cudaGetSymbolAddress((void**)&wgH, g_WgruH);
    cudaGetSymbolAddress((void**)&wgL, g_WgruL);
    cudaGetSymbolAddress((void**)&woH, g_WobsH);
    cudaGetSymbolAddress((void**)&woL, g_WobsL);
    cudaGetSymbolAddress((void**)&weH, g_WensH);
    cudaGetSymbolAddress((void**)&weL, g_WensL);
    cudaGetSymbolAddress((void**)&emH, g_embH);
    cudaGetSymbolAddress((void**)&emL, g_embL);
    cudaGetSymbolAddress((void**)&xH,  g_xH);
    cudaGetSymbolAddress((void**)&xL,  g_xL);
    cudaGetSymbolAddress((void**)&dH,  g_deterH);
    cudaGetSymbolAddress((void**)&dL,  g_deterL);
    cudaGetSymbolAddress((void**)&pxope, g_xope);
    {
        float* base0; cudaGetSymbolAddress((void**)&base0, g_pp0s);
        float* base1; cudaGetSymbolAddress((void**)&base1, g_pp1s);
        for (int c = 0; c < 4; c++) {
            pp0[c] = base0 + (size_t)c * B_ * 3072;
            pp1[c] = base1 + (size_t)c * B_ * 3072;
        }
    }

    static cudaStream_t s2 = 0;
    static cudaEvent_t e0 = 0, eW = 0, eEmb = 0;
    static int inited = 0;
    if (!inited) {
        cudaStreamCreateWithFlags(&s2, cudaStreamNonBlocking);
        cudaEventCreateWithFlags(&e0,   cudaEventDisableTiming);
        cudaEventCreateWithFlags(&eW,   cudaEventDisableTiming);
        cudaEventCreateWithFlags(&eEmb, cudaEventDisableTiming);
        cudaFuncSetAttribute(k_step,
                             cudaFuncAttributeMaxDynamicSharedMemorySize, 65536);
        inited = 1;
    }

    // ---- setup: main stream ----
    k_init<<<(B_ * DETER + 255) / 256, 256>>>();
    cudaEventRecord(e0, 0);
    k_split<<<4096, 256>>>(W_obs, woH, woL, 2560 * 1024);
    cudaEventRecord(eW, 0);
    k_split<<<4096, 256>>>(W_gru, wgH, wgL, 2048 * 3072);
    k_split<<<4096, 256>>>(W_ens, weH, weL, ENS * 1024 * 1024);
    k_transpose<<<(6 * 65536) / 256, 256>>>(W_obs_dist, W_ens_dist);
    k_inp0<<<B_, 256>>>(action, is_first, W_inp, b_inp);

    // ---- s2: embed split + xope GEMM ----
    cudaStreamWaitEvent(s2, e0, 0);
    k_split<<<8192, 256, 0, s2>>>(embed, emH, emL, B_ * T_ * EMBED);
    cudaStreamWaitEvent(s2, eW, 0);
    {
        ParamsTC p = {};
        p.s[0] = { emH, emL, EMBED,
                   woH + (size_t)1024 * 1024, woL + (size_t)1024 * 1024, 1024,
                   1536, nullptr, pxope, 1024, 256 };
        p.start[0] = 0; p.start[1] = 4096;
        p.nsub = 1;
        gemm_tc<<<4096, 128, 0, s2>>>(p);
    }
    cudaEventRecord(eEmb, s2);

    // ---- prologue: gruX(0) + gruD(0) in K=256 chunks (8 subs x 192 tiles) ----
    {
        ParamsTC p = {};
        for (int c = 0; c < 4; c++) {
            p.s[c] = { xH + c * 256, xL + c * 256, HIDDEN,
                       wgH + (size_t)(c * 256) * 3072,
                       wgL + (size_t)(c * 256) * 3072, 3072,
                       256, c == 0 ? b_gru : nullptr, pp0[c], 3072, 4 };
            p.s[4 + c] = { dH + c * 256, dL + c * 256, DETER,
                           wgH + (size_t)(1024 + c * 256) * 3072,
                           wgL + (size_t)(1024 + c * 256) * 3072, 3072,
                           256, nullptr, pp1[c], 3072, 4 };
        }
        for (int i = 0; i <= 8; i++) p.start[i] = i * 192;
        p.nsub = 8;
        gemm_tc<<<1536, 128>>>(p);
    }

    // xope must be ready before k_step(0) phase 2
    cudaStreamWaitEvent(0, eEmb, 0);

    for (int t = 0; t < T_; t++) {
        k_step<<<NCTA, 256, 65536>>>(
            t, t + 1 == T_, 384u * t,
            ens_idx, ln_g, ln_b, is_first,
            b_gru, b_obs, b_ens, b_obs_dist, b_ens_dist,
            eps_post, eps_prior, action, W_inp, b_inp, out);
    }
}